// round 2
// baseline (speedup 1.0000x reference)
#include <cuda_runtime.h>
#include <math.h>

// ---------------------------------------------------------------------------
// BCEDecorrelatedLoss — fused O(N^2) single pass + O(N) finalize.
//
// With normalized weights w (sum w = N), p_ij=|x_i-x_j|, q_ij=|y_i-y_j|:
//   asum[i] = sum_j w_j p_ij ,  bsum[i] = sum_j w_j q_ij ,
//   t[i]    = sum_j w_j p_ij q_ij
//   a0 = sum_i w_i asum_i / N^2 ,  alpha_i = asum_i/N
// Exact identities (derived by expanding the centered forms):
//   S_AA = 2N*sum(w x^2) - 2(sum w x)^2 - 2N*sum(w alpha^2) + N^2 a0^2
//   S_BB = (same with y/beta/b0)
//   S_AB = T - 2N*sum(w alpha beta) + N^2 a0 b0,  T = sum_i w_i t_i
//   disco = S_AB / sqrt(S_AA * S_BB)
// Only asum/bsum/t need the O(N^2) pass -> ONE fused kernel, f32x2 packed.
// Cancellation in S_AB is severe -> row sums accumulated via double atomics,
// finalize entirely in double.
// ---------------------------------------------------------------------------

#define MAXN 8192
#define CT    256   // threads per block (== j-tile size)
#define ITEMS 4     // i-rows per thread
#define CJT   256   // j-tile size

__device__ float  g_w[MAXN];
__device__ double g_asum[MAXN];
__device__ double g_bsum[MAXN];
__device__ double g_t[MAXN];
__device__ float  g_bce;

typedef unsigned long long u64;

__device__ __forceinline__ u64 pk2(float lo, float hi) {
    u64 r; asm("mov.b64 %0,{%1,%2};" : "=l"(r) : "f"(lo), "f"(hi)); return r;
}
__device__ __forceinline__ void upk2(u64 v, float& lo, float& hi) {
    asm("mov.b64 {%0,%1},%2;" : "=f"(lo), "=f"(hi) : "l"(v));
}
__device__ __forceinline__ u64 add2(u64 a, u64 b) {
    u64 r; asm("add.rn.f32x2 %0,%1,%2;" : "=l"(r) : "l"(a), "l"(b)); return r;
}
__device__ __forceinline__ u64 mul2(u64 a, u64 b) {
    u64 r; asm("mul.rn.f32x2 %0,%1,%2;" : "=l"(r) : "l"(a), "l"(b)); return r;
}
__device__ __forceinline__ u64 fma2(u64 a, u64 b, u64 c) {
    u64 r; asm("fma.rn.f32x2 %0,%1,%2,%3;" : "=l"(r) : "l"(a), "l"(b), "l"(c)); return r;
}
#define ABS2(v) ((v) & 0x7FFFFFFF7FFFFFFFULL)

// ---- block-wide reductions -------------------------------------------------
__device__ __forceinline__ float blockReduceF(float v) {
    __shared__ float s[32];
    int lane = threadIdx.x & 31, wid = threadIdx.x >> 5;
    #pragma unroll
    for (int o = 16; o; o >>= 1) v += __shfl_down_sync(0xffffffffu, v, o);
    if (lane == 0) s[wid] = v;
    __syncthreads();
    int nw = blockDim.x >> 5;
    float r = (threadIdx.x < nw) ? s[threadIdx.x] : 0.0f;
    if (wid == 0) {
        #pragma unroll
        for (int o = 16; o; o >>= 1) r += __shfl_down_sync(0xffffffffu, r, o);
        if (lane == 0) s[0] = r;
    }
    __syncthreads();
    float out = s[0];
    __syncthreads();
    return out;
}

__device__ __forceinline__ double blockReduceD(double v) {
    __shared__ double s[32];
    int lane = threadIdx.x & 31, wid = threadIdx.x >> 5;
    #pragma unroll
    for (int o = 16; o; o >>= 1) v += __shfl_down_sync(0xffffffffu, v, o);
    if (lane == 0) s[wid] = v;
    __syncthreads();
    int nw = blockDim.x >> 5;
    double r = (threadIdx.x < nw) ? s[threadIdx.x] : 0.0;
    if (wid == 0) {
        #pragma unroll
        for (int o = 16; o; o >>= 1) r += __shfl_down_sync(0xffffffffu, r, o);
        if (lane == 0) s[0] = r;
    }
    __syncthreads();
    double out = s[0];
    __syncthreads();
    return out;
}

// ---------------------------------------------------------------------------
// k1: zero accumulators, sum weights, BCE mean, normalized weights -> g_w
// ---------------------------------------------------------------------------
__global__ void k1(const float* __restrict__ outputs,
                   const float* __restrict__ labels,
                   const float* __restrict__ weights, int n) {
    int tid = threadIdx.x;
    for (int i = tid; i < n; i += blockDim.x) {
        g_asum[i] = 0.0; g_bsum[i] = 0.0; g_t[i] = 0.0;
    }
    float sw = 0.0f, sb = 0.0f;
    for (int i = tid; i < n; i += blockDim.x) {
        float x = outputs[i], y = labels[i], w = weights[i];
        sw += w;
        float sp = fmaxf(x, 0.0f) + log1pf(expf(-fabsf(x)));   // logaddexp(0,x)
        sb += (sp - x * y) * w;
    }
    float swt = blockReduceF(sw);
    float sbt = blockReduceF(sb);
    float scale = (float)n / swt;
    for (int i = tid; i < n; i += blockDim.x) g_w[i] = weights[i] * scale;
    if (tid == 0) g_bce = sbt / (float)n;
}

// ---------------------------------------------------------------------------
// k2: fused O(N^2) pass -> asum, bsum, t  (f32x2 packed math)
// grid: (n/(CT*ITEMS), n/CJT), CT threads
// ---------------------------------------------------------------------------
__global__ void __launch_bounds__(CT) k2(const float* __restrict__ x,
                                         const float* __restrict__ y, int n) {
    __shared__ __align__(8) float snx[CJT];
    __shared__ __align__(8) float sny[CJT];
    __shared__ __align__(8) float swj[CJT];
    int tid = threadIdx.x;

    // fill j tile (negated x,y so dx = xi + (-xj) via add2)
    {
        int j = blockIdx.y * CJT + tid;
        snx[tid] = -x[j];
        sny[tid] = -y[j];
        swj[tid] = g_w[j];
    }

    u64 xi2[ITEMS], yi2[ITEMS], sa2[ITEMS], sb2[ITEMS], st2[ITEMS];
    int ibase = blockIdx.x * (CT * ITEMS) + tid;
    #pragma unroll
    for (int k = 0; k < ITEMS; ++k) {
        int i = ibase + k * CT;
        float xv = x[i], yv = y[i];
        xi2[k] = pk2(xv, xv);
        yi2[k] = pk2(yv, yv);
        sa2[k] = 0ull; sb2[k] = 0ull; st2[k] = 0ull;
    }
    __syncthreads();

    const float2* nxp = (const float2*)snx;
    const float2* nyp = (const float2*)sny;
    const float2* wp  = (const float2*)swj;

    #pragma unroll 2
    for (int t = 0; t < CJT / 2; ++t) {
        float2 nx = nxp[t], ny = nyp[t], w = wp[t];
        u64 nxq = pk2(nx.x, nx.y);
        u64 nyq = pk2(ny.x, ny.y);
        u64 wq  = pk2(w.x,  w.y);
        #pragma unroll
        for (int k = 0; k < ITEMS; ++k) {
            u64 dx = add2(xi2[k], nxq);
            u64 dy = add2(yi2[k], nyq);
            u64 pr = mul2(dx, dy);                    // |dx||dy| = |dx*dy|
            sa2[k] = fma2(ABS2(dx), wq, sa2[k]);
            sb2[k] = fma2(ABS2(dy), wq, sb2[k]);
            st2[k] = fma2(ABS2(pr), wq, st2[k]);
        }
    }

    #pragma unroll
    for (int k = 0; k < ITEMS; ++k) {
        int i = ibase + k * CT;
        float lo, hi;
        upk2(sa2[k], lo, hi); atomicAdd(&g_asum[i], (double)lo + (double)hi);
        upk2(sb2[k], lo, hi); atomicAdd(&g_bsum[i], (double)lo + (double)hi);
        upk2(st2[k], lo, hi); atomicAdd(&g_t[i],    (double)lo + (double)hi);
    }
}

// ---------------------------------------------------------------------------
// k3: O(N) finalize in double; writes [bce, disco, tot]
// ---------------------------------------------------------------------------
__global__ void k3(const float* __restrict__ x, const float* __restrict__ y,
                   float* __restrict__ out, int n, int out_size) {
    int tid = threadIdx.x;
    double s1 = 0, s2 = 0, s3 = 0, s4 = 0, s5 = 0;
    double s6 = 0, s7 = 0, s8 = 0, s9 = 0, s10 = 0;
    for (int i = tid; i < n; i += blockDim.x) {
        double w  = (double)g_w[i];
        double as = g_asum[i];
        double bs = g_bsum[i];
        double ti = g_t[i];
        double xv = (double)x[i];
        double yv = (double)y[i];
        s1 += w * as;            // N^2 a0
        s2 += w * bs;            // N^2 b0
        s3 += w * as * as;       // N^2 * sum(w alpha^2)
        s4 += w * bs * bs;
        s5 += w * as * bs;       // N^2 * sum(w alpha beta)
        s6 += w * ti;            // T
        s7 += w * xv;
        s8 += w * xv * xv;
        s9 += w * yv;
        s10 += w * yv * yv;
    }
    s1 = blockReduceD(s1);   s2 = blockReduceD(s2);
    s3 = blockReduceD(s3);   s4 = blockReduceD(s4);
    s5 = blockReduceD(s5);   s6 = blockReduceD(s6);
    s7 = blockReduceD(s7);   s8 = blockReduceD(s8);
    s9 = blockReduceD(s9);   s10 = blockReduceD(s10);

    if (tid == 0) {
        double Nn = (double)n;
        double N2 = Nn * Nn;
        double a0 = s1 / N2, b0 = s2 / N2;
        // S_AB = T - 2N*sum(w a b) + N^2 a0 b0 ; sum(w a b) = s5/N^2
        double SAB = s6 - 2.0 * s5 / Nn + a0 * b0 * N2;
        double SAA = 2.0 * Nn * s8 - 2.0 * s7 * s7 - 2.0 * s3 / Nn + a0 * a0 * N2;
        double SBB = 2.0 * Nn * s10 - 2.0 * s9 * s9 - 2.0 * s4 / Nn + b0 * b0 * N2;
        double disco = SAB / sqrt(SAA * SBB);
        float bce = g_bce;
        float vals[3];
        vals[0] = bce;
        vals[1] = (float)disco;
        vals[2] = bce + 0.1f * (float)disco;
        int m = out_size < 3 ? out_size : 3;
        for (int i = 0; i < m; ++i) out[i] = vals[i];
        for (int i = 3; i < out_size; ++i) out[i] = 0.0f;
    }
}

// ---------------------------------------------------------------------------
extern "C" void kernel_launch(void* const* d_in, const int* in_sizes, int n_in,
                              void* d_out, int out_size) {
    const float* outputs = (const float*)d_in[0];
    const float* labels  = (const float*)d_in[1];
    const float* event   = (const float*)d_in[2];
    const float* weights = (const float*)d_in[3];
    int n = in_sizes[0];

    k1<<<1, 1024>>>(outputs, labels, weights, n);

    dim3 g2(n / (CT * ITEMS), n / CJT);
    k2<<<g2, CT>>>(outputs, event, n);

    k3<<<1, 1024>>>(outputs, event, (float*)d_out, n, out_size);
}